// round 4
// baseline (speedup 1.0000x reference)
#include <cuda_runtime.h>
#include <cuda_fp16.h>

#define NN 25000
#define EE 400000
#define NCHUNK ((NN + 63) / 64)   // 391

// Z stored fp16, 25000 rows x 1024 halves = 51.2 MB (L2-resident).
// Row layout (chunked for K2): uint4 chunk index ci = i*32 + l (i=0..3, l=lane):
//   halves[0..3] = Z[k0, hq*4 .. hq*4+3],  halves[4..7] = Z[k0+4, same h-quad]
//   where k0 = 8*i + (l>>3), hq = (l&7).
__device__ __align__(16) __half g_Zh[NN * 1024];

// packed fp32x2 helpers (Blackwell dual-FMA, PTX-only)
__device__ __forceinline__ unsigned long long pk2(float lo, float hi) {
    unsigned long long r;
    asm("mov.b64 %0, {%1,%2};" : "=l"(r) : "f"(lo), "f"(hi));
    return r;
}
__device__ __forceinline__ void upk2(float& lo, float& hi, unsigned long long v) {
    asm("mov.b64 {%0,%1}, %2;" : "=f"(lo), "=f"(hi) : "l"(v));
}
__device__ __forceinline__ unsigned long long ffma2(unsigned long long a,
                                                    unsigned long long b,
                                                    unsigned long long c) {
    unsigned long long d;
    asm("fma.rn.f32x2 %0, %1, %2, %3;" : "=l"(d) : "l"(a), "l"(b), "l"(c));
    return d;
}

// ---------------------------------------------------------------------------
// K1 (persistent): stage G = transposed edge_W (swizzled) ONCE per CTA, then
// loop node-chunks of 64. Z = x @ G stored fp16 (chunked layout above);
// out = x @ node_W^T. Grid = 148 CTAs (one wave, 1 CTA/SM @ 144.5 KB smem).
// ---------------------------------------------------------------------------
__global__ void __launch_bounds__(256, 1)
k1_build_Z(const float* __restrict__ x, const float* __restrict__ edge_W,
           const float* __restrict__ node_W, float* __restrict__ out) {
    extern __shared__ float sm[];
    float* Gs  = sm;               // 32 x 1024 swizzled, 128 KB
    float* xs  = Gs + 32 * 1024;   // x transposed [32][72]
    float* nws = xs + 32 * 72;     // node_W [32][33]

    const int t  = threadIdx.x;
    const int tx = t & 31;
    const int ty = t >> 5;

    // ---- one-time staging: G (transpose k<->h per d-block, SW128 swizzle) ----
    for (int i = t; i < 32 * 1024; i += 256) {
        const int d   = i >> 10;
        const int rem = i & 1023;
        const int h   = rem >> 5;
        const int k   = rem & 31;
        const int cb  = ((k << 5) | h) << 2;
        const int sw  = cb ^ ((cb >> 3) & 0x70);
        Gs[(d << 10) + (sw >> 2)] = edge_W[i];
    }
    for (int i = t; i < 1024; i += 256) {
        nws[(i >> 5) * 33 + (i & 31)] = node_W[i];
    }

    for (int chunk = blockIdx.x; chunk < NCHUNK; chunk += gridDim.x) {
        const int node0 = chunk * 64;

        __syncthreads();   // first iter: covers G staging; later: protects xs
        // stage xs (x transposed for these 64 nodes)
        for (int i = t; i < 64 * 8; i += 256) {
            const int jl = i >> 3;
            const int d4 = (i & 7) << 2;
            const int j  = node0 + jl;
            float4 v = make_float4(0.f, 0.f, 0.f, 0.f);
            if (j < NN) v = *reinterpret_cast<const float4*>(x + j * 32 + d4);
            xs[(d4 + 0) * 72 + jl] = v.x;
            xs[(d4 + 1) * 72 + jl] = v.y;
            xs[(d4 + 2) * 72 + jl] = v.z;
            xs[(d4 + 3) * 72 + jl] = v.w;
        }
        __syncthreads();

        // out init: warp ty -> nodes node0+ty*8..+7, lane tx = h
        {
            float accn[8];
#pragma unroll
            for (int n = 0; n < 8; n++) accn[n] = 0.f;
#pragma unroll 4
            for (int d = 0; d < 32; d++) {
                const float w = nws[tx * 33 + d];
#pragma unroll
                for (int n = 0; n < 8; n++)
                    accn[n] += xs[d * 72 + ty * 8 + n] * w;
            }
#pragma unroll
            for (int n = 0; n < 8; n++) {
                const int j = node0 + ty * 8 + n;
                if (j < NN) out[j * 32 + tx] = accn[n];
            }
        }

        // Z GEMM: 8 col-tiles of 128; node-pairs packed in f32x2
        for (int tile = 0; tile < 8; tile++) {
            const int c   = tile * 128 + tx * 4;
            const int cb  = c << 2;
            const int swi = (cb ^ ((cb >> 3) & 0x70)) >> 2;

            unsigned long long acc2[4][4];
#pragma unroll
            for (int np = 0; np < 4; np++)
#pragma unroll
                for (int i = 0; i < 4; i++) acc2[np][i] = 0ull;

#pragma unroll 4
            for (int d = 0; d < 32; d++) {
                const float4 b = *reinterpret_cast<const float4*>(&Gs[(d << 10) + swi]);
                const unsigned long long bc[4] = {pk2(b.x, b.x), pk2(b.y, b.y),
                                                  pk2(b.z, b.z), pk2(b.w, b.w)};
                const unsigned long long* ap =
                    reinterpret_cast<const unsigned long long*>(&xs[d * 72 + ty * 8]);
#pragma unroll
                for (int np = 0; np < 4; np++) {
                    const unsigned long long a2 = ap[np];
#pragma unroll
                    for (int i = 0; i < 4; i++)
                        acc2[np][i] = ffma2(a2, bc[i], acc2[np][i]);
                }
            }

            // fp16 store into chunked layout:
            // uint2 slot = ((tile>>1)*32 + tx)*2 + (tile&1)
            const int slot = ((tile >> 1) * 32 + tx) * 2 + (tile & 1);
#pragma unroll
            for (int np = 0; np < 4; np++) {
#pragma unroll
                for (int s = 0; s < 2; s++) {
                    const int n = np * 2 + s;
                    const int j = node0 + ty * 8 + n;
                    if (j < NN) {
                        float v0, v1, v2, v3, dummy;
                        if (s == 0) {
                            upk2(v0, dummy, acc2[np][0]);
                            upk2(v1, dummy, acc2[np][1]);
                            upk2(v2, dummy, acc2[np][2]);
                            upk2(v3, dummy, acc2[np][3]);
                        } else {
                            upk2(dummy, v0, acc2[np][0]);
                            upk2(dummy, v1, acc2[np][1]);
                            upk2(dummy, v2, acc2[np][2]);
                            upk2(dummy, v3, acc2[np][3]);
                        }
                        __half2 h01 = __floats2half2_rn(v0, v1);
                        __half2 h23 = __floats2half2_rn(v2, v3);
                        uint2 pkd = make_uint2(*reinterpret_cast<unsigned*>(&h01),
                                               *reinterpret_cast<unsigned*>(&h23));
                        reinterpret_cast<uint2*>(g_Zh)[j * 256 + slot] = pkd;
                    }
                }
            }
        }
    }
}

// ---------------------------------------------------------------------------
// K2: warp per edge. All 4 z LDG.128 front-batched into registers (MLP=4),
// all 8 ek shfls hoisted, then pure FMA. ea streamed with __ldcg (no L1
// pollution - keep L1 for Z). Butterfly ^8/^16, lanes 0..7 red.v4.
// __launch_bounds__(256,4): allow up to 64 regs (32 warps/SM still).
// ---------------------------------------------------------------------------
__global__ void __launch_bounds__(256, 4)
k2_edges(const float* __restrict__ ea, const int* __restrict__ ei,
         float* __restrict__ out) {
    const int e    = blockIdx.x * 8 + (threadIdx.x >> 5);
    const int lane = threadIdx.x & 31;

    const int src = ei[e];
    const int dst = ei[EE + e];
    const float eav = __ldcg(&ea[e * 32 + lane]);

    const uint4* Zp = reinterpret_cast<const uint4*>(g_Zh + src * 1024);
    // front-batch all Z loads (16 regs, 4 independent LDGs in flight)
    const uint4 z0 = Zp[lane];
    const uint4 z1 = Zp[32 + lane];
    const uint4 z2 = Zp[64 + lane];
    const uint4 z3 = Zp[96 + lane];

    // hoist all ek broadcasts (depend only on eav)
    const int kres = lane >> 3;
    float ek[8];
#pragma unroll
    for (int i = 0; i < 4; i++) {
        ek[2 * i]     = __shfl_sync(0xffffffffu, eav, i * 8 + kres);
        ek[2 * i + 1] = __shfl_sync(0xffffffffu, eav, i * 8 + 4 + kres);
    }

    float4 acc = make_float4(0.f, 0.f, 0.f, 0.f);
    const uint4 zz[4] = {z0, z1, z2, z3};
#pragma unroll
    for (int i = 0; i < 4; i++) {
        const float2 f01 = __half22float2(*reinterpret_cast<const __half2*>(&zz[i].x));
        const float2 f23 = __half22float2(*reinterpret_cast<const __half2*>(&zz[i].y));
        const float2 g01 = __half22float2(*reinterpret_cast<const __half2*>(&zz[i].z));
        const float2 g23 = __half22float2(*reinterpret_cast<const __half2*>(&zz[i].w));
        acc.x += ek[2 * i] * f01.x + ek[2 * i + 1] * g01.x;
        acc.y += ek[2 * i] * f01.y + ek[2 * i + 1] * g01.y;
        acc.z += ek[2 * i] * f23.x + ek[2 * i + 1] * g23.x;
        acc.w += ek[2 * i] * f23.y + ek[2 * i + 1] * g23.y;
    }
    acc.x += __shfl_xor_sync(0xffffffffu, acc.x, 8);
    acc.y += __shfl_xor_sync(0xffffffffu, acc.y, 8);
    acc.z += __shfl_xor_sync(0xffffffffu, acc.z, 8);
    acc.w += __shfl_xor_sync(0xffffffffu, acc.w, 8);
    acc.x += __shfl_xor_sync(0xffffffffu, acc.x, 16);
    acc.y += __shfl_xor_sync(0xffffffffu, acc.y, 16);
    acc.z += __shfl_xor_sync(0xffffffffu, acc.z, 16);
    acc.w += __shfl_xor_sync(0xffffffffu, acc.w, 16);

    if (lane < 8) {
        float* p = out + dst * 32 + lane * 4;
        asm volatile("red.global.add.v4.f32 [%0], {%1,%2,%3,%4};"
                     :: "l"(p), "f"(acc.x), "f"(acc.y), "f"(acc.z), "f"(acc.w)
                     : "memory");
    }
}

// ---------------------------------------------------------------------------
extern "C" void kernel_launch(void* const* d_in, const int* in_sizes, int n_in,
                              void* d_out, int out_size) {
    const float* x          = (const float*)d_in[0];  // [25000,32]
    const float* edge_attr  = (const float*)d_in[1];  // [400000,32]
    const float* edge_W     = (const float*)d_in[2];  // [1024,32]
    const float* node_W     = (const float*)d_in[3];  // [32,32]
    const int*   edge_index = (const int*)d_in[4];    // [2,400000]
    float* out = (float*)d_out;

    const size_t smem1 = (32 * 1024 + 32 * 72 + 32 * 33) * sizeof(float); // 144.5 KB
    cudaFuncSetAttribute(k1_build_Z, cudaFuncAttributeMaxDynamicSharedMemorySize,
                         (int)smem1);

    k1_build_Z<<<148, 256, smem1>>>(x, edge_W, node_W, out);
    k2_edges<<<EE / 8, 256>>>(edge_attr, edge_index, out);
}

// round 5
// speedup vs baseline: 1.0881x; 1.0881x over previous
#include <cuda_runtime.h>
#include <cuda_fp16.h>

#define NN 25000
#define EE 400000
#define NCHUNK ((NN + 63) / 64)   // 391

// Z stored fp16, 25000 rows x 1024 halves = 51.2 MB (L2-resident).
// Row layout (chunked for K2): uint4 chunk index ci = i*32 + l (i=0..3, l=lane):
//   halves[0..3] = Z[k0, hq*4 .. hq*4+3],  halves[4..7] = Z[k0+4, same h-quad]
//   where k0 = 8*i + (l>>3), hq = (l&7).
__device__ __align__(16) __half g_Zh[NN * 1024];

// packed fp32x2 helpers (Blackwell dual-FMA, PTX-only)
__device__ __forceinline__ unsigned long long pk2(float lo, float hi) {
    unsigned long long r;
    asm("mov.b64 %0, {%1,%2};" : "=l"(r) : "f"(lo), "f"(hi));
    return r;
}
__device__ __forceinline__ void upk2(float& lo, float& hi, unsigned long long v) {
    asm("mov.b64 {%0,%1}, %2;" : "=f"(lo), "=f"(hi) : "l"(v));
}
__device__ __forceinline__ unsigned long long ffma2(unsigned long long a,
                                                    unsigned long long b,
                                                    unsigned long long c) {
    unsigned long long d;
    asm("fma.rn.f32x2 %0, %1, %2, %3;" : "=l"(d) : "l"(a), "l"(b), "l"(c));
    return d;
}

// ---------------------------------------------------------------------------
// K1 (persistent): stage G = transposed edge_W (swizzled) ONCE per CTA, then
// loop node-chunks of 64. Z = x @ G stored fp16 (chunked layout, coalesced
// uint4 stores via tile-pairing); out = x @ node_W^T. Grid = 148 CTAs.
// ---------------------------------------------------------------------------
__global__ void __launch_bounds__(256, 1)
k1_build_Z(const float* __restrict__ x, const float* __restrict__ edge_W,
           const float* __restrict__ node_W, float* __restrict__ out) {
    extern __shared__ float sm[];
    float* Gs  = sm;               // 32 x 1024 swizzled, 128 KB
    float* xs  = Gs + 32 * 1024;   // x transposed [32][72]
    float* nws = xs + 32 * 72;     // node_W [32][33]

    const int t  = threadIdx.x;
    const int tx = t & 31;
    const int ty = t >> 5;

    // ---- one-time staging: G (transpose k<->h per d-block, SW128 swizzle) ----
    for (int i = t; i < 32 * 1024; i += 256) {
        const int d   = i >> 10;
        const int rem = i & 1023;
        const int h   = rem >> 5;
        const int k   = rem & 31;
        const int cb  = ((k << 5) | h) << 2;
        const int sw  = cb ^ ((cb >> 3) & 0x70);
        Gs[(d << 10) + (sw >> 2)] = edge_W[i];
    }
    for (int i = t; i < 1024; i += 256) {
        nws[(i >> 5) * 33 + (i & 31)] = node_W[i];
    }

    for (int chunk = blockIdx.x; chunk < NCHUNK; chunk += gridDim.x) {
        const int node0 = chunk * 64;

        __syncthreads();   // first iter: covers G staging; later: protects xs
        for (int i = t; i < 64 * 8; i += 256) {
            const int jl = i >> 3;
            const int d4 = (i & 7) << 2;
            const int j  = node0 + jl;
            float4 v = make_float4(0.f, 0.f, 0.f, 0.f);
            if (j < NN) v = *reinterpret_cast<const float4*>(x + j * 32 + d4);
            xs[(d4 + 0) * 72 + jl] = v.x;
            xs[(d4 + 1) * 72 + jl] = v.y;
            xs[(d4 + 2) * 72 + jl] = v.z;
            xs[(d4 + 3) * 72 + jl] = v.w;
        }
        __syncthreads();

        // out init: warp ty -> nodes node0+ty*8..+7, lane tx = h
        {
            float accn[8];
#pragma unroll
            for (int n = 0; n < 8; n++) accn[n] = 0.f;
#pragma unroll 4
            for (int d = 0; d < 32; d++) {
                const float w = nws[tx * 33 + d];
#pragma unroll
                for (int n = 0; n < 8; n++)
                    accn[n] += xs[d * 72 + ty * 8 + n] * w;
            }
#pragma unroll
            for (int n = 0; n < 8; n++) {
                const int j = node0 + ty * 8 + n;
                if (j < NN) out[j * 32 + tx] = accn[n];
            }
        }

        // Z GEMM: 4 tile-PAIRS (tiles 2tp, 2tp+1); node-pairs packed in f32x2.
        // Pairing lets the epilogue emit full uint4 (coalesced 512B/warp) stores.
        for (int tp = 0; tp < 4; tp++) {
            const int c0   = tp * 256 + tx * 4;          // even tile cols
            const int cb0  = c0 << 2;
            const int swi0 = (cb0 ^ ((cb0 >> 3) & 0x70)) >> 2;
            const int c1   = c0 + 128;                   // odd tile cols
            const int cb1  = c1 << 2;
            const int swi1 = (cb1 ^ ((cb1 >> 3) & 0x70)) >> 2;

            unsigned long long acc2[2][4][4];  // [sub-tile][node-pair][col]
#pragma unroll
            for (int st = 0; st < 2; st++)
#pragma unroll
                for (int np = 0; np < 4; np++)
#pragma unroll
                    for (int i = 0; i < 4; i++) acc2[st][np][i] = 0ull;

#pragma unroll 4
            for (int d = 0; d < 32; d++) {
                const float4 b0 = *reinterpret_cast<const float4*>(&Gs[(d << 10) + swi0]);
                const float4 b1 = *reinterpret_cast<const float4*>(&Gs[(d << 10) + swi1]);
                const unsigned long long bc0[4] = {pk2(b0.x, b0.x), pk2(b0.y, b0.y),
                                                   pk2(b0.z, b0.z), pk2(b0.w, b0.w)};
                const unsigned long long bc1[4] = {pk2(b1.x, b1.x), pk2(b1.y, b1.y),
                                                   pk2(b1.z, b1.z), pk2(b1.w, b1.w)};
                const unsigned long long* ap =
                    reinterpret_cast<const unsigned long long*>(&xs[d * 72 + ty * 8]);
#pragma unroll
                for (int np = 0; np < 4; np++) {
                    const unsigned long long a2 = ap[np];
#pragma unroll
                    for (int i = 0; i < 4; i++) {
                        acc2[0][np][i] = ffma2(a2, bc0[i], acc2[0][np][i]);
                        acc2[1][np][i] = ffma2(a2, bc1[i], acc2[1][np][i]);
                    }
                }
            }

            // Coalesced store: uint4 index = j*128 + tp*32 + tx
            // (== old uint2 pair j*256 + (tp*32+tx)*2 + {0,1}; even tile ->
            //  halves[0..3] (k0), odd tile -> halves[4..7] (k0+4))
            const int slot4 = tp * 32 + tx;
#pragma unroll
            for (int np = 0; np < 4; np++) {
#pragma unroll
                for (int s = 0; s < 2; s++) {
                    const int j = node0 + ty * 8 + np * 2 + s;
                    if (j < NN) {
                        float v0, v1, v2, v3, w0, w1, w2, w3, dm;
                        if (s == 0) {
                            upk2(v0, dm, acc2[0][np][0]);
                            upk2(v1, dm, acc2[0][np][1]);
                            upk2(v2, dm, acc2[0][np][2]);
                            upk2(v3, dm, acc2[0][np][3]);
                            upk2(w0, dm, acc2[1][np][0]);
                            upk2(w1, dm, acc2[1][np][1]);
                            upk2(w2, dm, acc2[1][np][2]);
                            upk2(w3, dm, acc2[1][np][3]);
                        } else {
                            upk2(dm, v0, acc2[0][np][0]);
                            upk2(dm, v1, acc2[0][np][1]);
                            upk2(dm, v2, acc2[0][np][2]);
                            upk2(dm, v3, acc2[0][np][3]);
                            upk2(dm, w0, acc2[1][np][0]);
                            upk2(dm, w1, acc2[1][np][1]);
                            upk2(dm, w2, acc2[1][np][2]);
                            upk2(dm, w3, acc2[1][np][3]);
                        }
                        __half2 h01 = __floats2half2_rn(v0, v1);
                        __half2 h23 = __floats2half2_rn(v2, v3);
                        __half2 h45 = __floats2half2_rn(w0, w1);
                        __half2 h67 = __floats2half2_rn(w2, w3);
                        uint4 pkd = make_uint4(*reinterpret_cast<unsigned*>(&h01),
                                               *reinterpret_cast<unsigned*>(&h23),
                                               *reinterpret_cast<unsigned*>(&h45),
                                               *reinterpret_cast<unsigned*>(&h67));
                        reinterpret_cast<uint4*>(g_Zh)[j * 128 + slot4] = pkd;
                    }
                }
            }
        }
    }
}

// ---------------------------------------------------------------------------
// K2: EXACT R3 version (regs=32, occ 87%, 82.6us measured). Warp per edge.
// ---------------------------------------------------------------------------
__global__ void __launch_bounds__(256)
k2_edges(const float* __restrict__ ea, const int* __restrict__ ei,
         float* __restrict__ out) {
    const int e    = blockIdx.x * 8 + (threadIdx.x >> 5);
    const int lane = threadIdx.x & 31;
    if (e >= EE) return;

    const int src = ei[e];
    const int dst = ei[EE + e];
    const float eav = ea[e * 32 + lane];

    const uint4* Zp = reinterpret_cast<const uint4*>(g_Zh + src * 1024);
    const int kres = lane >> 3;
    float4 acc = make_float4(0.f, 0.f, 0.f, 0.f);
#pragma unroll
    for (int i = 0; i < 4; i++) {
        const uint4 z = Zp[i * 32 + lane];
        const float ek0 = __shfl_sync(0xffffffffu, eav, i * 8 + kres);
        const float ek1 = __shfl_sync(0xffffffffu, eav, i * 8 + 4 + kres);
        const float2 f01 = __half22float2(*reinterpret_cast<const __half2*>(&z.x));
        const float2 f23 = __half22float2(*reinterpret_cast<const __half2*>(&z.y));
        const float2 g01 = __half22float2(*reinterpret_cast<const __half2*>(&z.z));
        const float2 g23 = __half22float2(*reinterpret_cast<const __half2*>(&z.w));
        acc.x += ek0 * f01.x + ek1 * g01.x;
        acc.y += ek0 * f01.y + ek1 * g01.y;
        acc.z += ek0 * f23.x + ek1 * g23.x;
        acc.w += ek0 * f23.y + ek1 * g23.y;
    }
    acc.x += __shfl_xor_sync(0xffffffffu, acc.x, 8);
    acc.y += __shfl_xor_sync(0xffffffffu, acc.y, 8);
    acc.z += __shfl_xor_sync(0xffffffffu, acc.z, 8);
    acc.w += __shfl_xor_sync(0xffffffffu, acc.w, 8);
    acc.x += __shfl_xor_sync(0xffffffffu, acc.x, 16);
    acc.y += __shfl_xor_sync(0xffffffffu, acc.y, 16);
    acc.z += __shfl_xor_sync(0xffffffffu, acc.z, 16);
    acc.w += __shfl_xor_sync(0xffffffffu, acc.w, 16);

    if (lane < 8) {
        float* p = out + dst * 32 + lane * 4;
        asm volatile("red.global.add.v4.f32 [%0], {%1,%2,%3,%4};"
                     :: "l"(p), "f"(acc.x), "f"(acc.y), "f"(acc.z), "f"(acc.w)
                     : "memory");
    }
}

// ---------------------------------------------------------------------------
extern "C" void kernel_launch(void* const* d_in, const int* in_sizes, int n_in,
                              void* d_out, int out_size) {
    const float* x          = (const float*)d_in[0];  // [25000,32]
    const float* edge_attr  = (const float*)d_in[1];  // [400000,32]
    const float* edge_W     = (const float*)d_in[2];  // [1024,32]
    const float* node_W     = (const float*)d_in[3];  // [32,32]
    const int*   edge_index = (const int*)d_in[4];    // [2,400000]
    float* out = (float*)d_out;

    const size_t smem1 = (32 * 1024 + 32 * 72 + 32 * 33) * sizeof(float); // 144.5 KB
    cudaFuncSetAttribute(k1_build_Z, cudaFuncAttributeMaxDynamicSharedMemorySize,
                         (int)smem1);

    k1_build_Z<<<148, 256, smem1>>>(x, edge_W, node_W, out);
    k2_edges<<<EE / 8, 256>>>(edge_attr, edge_index, out);
}

// round 6
// speedup vs baseline: 1.1344x; 1.0425x over previous
#include <cuda_runtime.h>
#include <cuda_fp16.h>

#define NN 25000
#define EE 400000
#define NCHUNK ((NN + 63) / 64)   // 391

// Z stored fp16, 25000 rows x 1024 halves = 51.2 MB (L2-resident).
// Row layout (chunked for K2): uint4 chunk index ci = i*32 + l (i=0..3, l=lane):
//   halves[0..3] = Z[k0, hq*4 .. hq*4+3],  halves[4..7] = Z[k0+4, same h-quad]
//   where k0 = 8*i + (l>>3), hq = (l&7).
__device__ __align__(16) __half g_Zh[NN * 1024];

// packed fp32x2 helpers (Blackwell dual-FMA, PTX-only)
__device__ __forceinline__ unsigned long long pk2(float lo, float hi) {
    unsigned long long r;
    asm("mov.b64 %0, {%1,%2};" : "=l"(r) : "f"(lo), "f"(hi));
    return r;
}
__device__ __forceinline__ void upk2(float& lo, float& hi, unsigned long long v) {
    asm("mov.b64 {%0,%1}, %2;" : "=f"(lo), "=f"(hi) : "l"(v));
}
__device__ __forceinline__ unsigned long long ffma2(unsigned long long a,
                                                    unsigned long long b,
                                                    unsigned long long c) {
    unsigned long long d;
    asm("fma.rn.f32x2 %0, %1, %2, %3;" : "=l"(d) : "l"(a), "l"(b), "l"(c));
    return d;
}

// ---------------------------------------------------------------------------
// K1 (persistent, unchanged from R5): stage G once, loop node-chunks of 64.
// ---------------------------------------------------------------------------
__global__ void __launch_bounds__(256, 1)
k1_build_Z(const float* __restrict__ x, const float* __restrict__ edge_W,
           const float* __restrict__ node_W, float* __restrict__ out) {
    extern __shared__ float sm[];
    float* Gs  = sm;               // 32 x 1024 swizzled, 128 KB
    float* xs  = Gs + 32 * 1024;   // x transposed [32][72]
    float* nws = xs + 32 * 72;     // node_W [32][33]

    const int t  = threadIdx.x;
    const int tx = t & 31;
    const int ty = t >> 5;

    for (int i = t; i < 32 * 1024; i += 256) {
        const int d   = i >> 10;
        const int rem = i & 1023;
        const int h   = rem >> 5;
        const int k   = rem & 31;
        const int cb  = ((k << 5) | h) << 2;
        const int sw  = cb ^ ((cb >> 3) & 0x70);
        Gs[(d << 10) + (sw >> 2)] = edge_W[i];
    }
    for (int i = t; i < 1024; i += 256) {
        nws[(i >> 5) * 33 + (i & 31)] = node_W[i];
    }

    for (int chunk = blockIdx.x; chunk < NCHUNK; chunk += gridDim.x) {
        const int node0 = chunk * 64;

        __syncthreads();
        for (int i = t; i < 64 * 8; i += 256) {
            const int jl = i >> 3;
            const int d4 = (i & 7) << 2;
            const int j  = node0 + jl;
            float4 v = make_float4(0.f, 0.f, 0.f, 0.f);
            if (j < NN) v = *reinterpret_cast<const float4*>(x + j * 32 + d4);
            xs[(d4 + 0) * 72 + jl] = v.x;
            xs[(d4 + 1) * 72 + jl] = v.y;
            xs[(d4 + 2) * 72 + jl] = v.z;
            xs[(d4 + 3) * 72 + jl] = v.w;
        }
        __syncthreads();

        {
            float accn[8];
#pragma unroll
            for (int n = 0; n < 8; n++) accn[n] = 0.f;
#pragma unroll 4
            for (int d = 0; d < 32; d++) {
                const float w = nws[tx * 33 + d];
#pragma unroll
                for (int n = 0; n < 8; n++)
                    accn[n] += xs[d * 72 + ty * 8 + n] * w;
            }
#pragma unroll
            for (int n = 0; n < 8; n++) {
                const int j = node0 + ty * 8 + n;
                if (j < NN) out[j * 32 + tx] = accn[n];
            }
        }

        for (int tp = 0; tp < 4; tp++) {
            const int c0   = tp * 256 + tx * 4;
            const int cb0  = c0 << 2;
            const int swi0 = (cb0 ^ ((cb0 >> 3) & 0x70)) >> 2;
            const int c1   = c0 + 128;
            const int cb1  = c1 << 2;
            const int swi1 = (cb1 ^ ((cb1 >> 3) & 0x70)) >> 2;

            unsigned long long acc2[2][4][4];
#pragma unroll
            for (int st = 0; st < 2; st++)
#pragma unroll
                for (int np = 0; np < 4; np++)
#pragma unroll
                    for (int i = 0; i < 4; i++) acc2[st][np][i] = 0ull;

#pragma unroll 4
            for (int d = 0; d < 32; d++) {
                const float4 b0 = *reinterpret_cast<const float4*>(&Gs[(d << 10) + swi0]);
                const float4 b1 = *reinterpret_cast<const float4*>(&Gs[(d << 10) + swi1]);
                const unsigned long long bc0[4] = {pk2(b0.x, b0.x), pk2(b0.y, b0.y),
                                                   pk2(b0.z, b0.z), pk2(b0.w, b0.w)};
                const unsigned long long bc1[4] = {pk2(b1.x, b1.x), pk2(b1.y, b1.y),
                                                   pk2(b1.z, b1.z), pk2(b1.w, b1.w)};
                const unsigned long long* ap =
                    reinterpret_cast<const unsigned long long*>(&xs[d * 72 + ty * 8]);
#pragma unroll
                for (int np = 0; np < 4; np++) {
                    const unsigned long long a2 = ap[np];
#pragma unroll
                    for (int i = 0; i < 4; i++) {
                        acc2[0][np][i] = ffma2(a2, bc0[i], acc2[0][np][i]);
                        acc2[1][np][i] = ffma2(a2, bc1[i], acc2[1][np][i]);
                    }
                }
            }

            const int slot4 = tp * 32 + tx;
#pragma unroll
            for (int np = 0; np < 4; np++) {
#pragma unroll
                for (int s = 0; s < 2; s++) {
                    const int j = node0 + ty * 8 + np * 2 + s;
                    if (j < NN) {
                        float v0, v1, v2, v3, w0, w1, w2, w3, dm;
                        if (s == 0) {
                            upk2(v0, dm, acc2[0][np][0]);
                            upk2(v1, dm, acc2[0][np][1]);
                            upk2(v2, dm, acc2[0][np][2]);
                            upk2(v3, dm, acc2[0][np][3]);
                            upk2(w0, dm, acc2[1][np][0]);
                            upk2(w1, dm, acc2[1][np][1]);
                            upk2(w2, dm, acc2[1][np][2]);
                            upk2(w3, dm, acc2[1][np][3]);
                        } else {
                            upk2(dm, v0, acc2[0][np][0]);
                            upk2(dm, v1, acc2[0][np][1]);
                            upk2(dm, v2, acc2[0][np][2]);
                            upk2(dm, v3, acc2[0][np][3]);
                            upk2(dm, w0, acc2[1][np][0]);
                            upk2(dm, w1, acc2[1][np][1]);
                            upk2(dm, w2, acc2[1][np][2]);
                            upk2(dm, w3, acc2[1][np][3]);
                        }
                        __half2 h01 = __floats2half2_rn(v0, v1);
                        __half2 h23 = __floats2half2_rn(v2, v3);
                        __half2 h45 = __floats2half2_rn(w0, w1);
                        __half2 h67 = __floats2half2_rn(w2, w3);
                        uint4 pkd = make_uint4(*reinterpret_cast<unsigned*>(&h01),
                                               *reinterpret_cast<unsigned*>(&h23),
                                               *reinterpret_cast<unsigned*>(&h45),
                                               *reinterpret_cast<unsigned*>(&h67));
                        reinterpret_cast<uint4*>(g_Zh)[j * 128 + slot4] = pkd;
                    }
                }
            }
        }
    }
}

// ---------------------------------------------------------------------------
// K2: warp per edge, fp16 HFMA2 inner loop. Two independent 4-term half2
// chains (A: chunks 0-1, B: chunks 2-3) merged in fp32, then fp32 butterfly.
// ek broadcast as pre-packed half2(ek,ek) via one shfl per k.
// ---------------------------------------------------------------------------
__global__ void __launch_bounds__(256)
k2_edges(const float* __restrict__ ea, const int* __restrict__ ei,
         float* __restrict__ out) {
    const int e    = blockIdx.x * 8 + (threadIdx.x >> 5);
    const int lane = threadIdx.x & 31;
    if (e >= EE) return;

    const int src = ei[e];
    const int dst = ei[EE + e];
    const float eav = ea[e * 32 + lane];
    const __half2 eavh2 = __floats2half2_rn(eav, eav);
    const unsigned ebits = *reinterpret_cast<const unsigned*>(&eavh2);

    const uint4* Zp = reinterpret_cast<const uint4*>(g_Zh + src * 1024);
    const int kres = lane >> 3;

    const __half2 hz = __floats2half2_rn(0.f, 0.f);
    __half2 a01 = hz, a23 = hz, b01 = hz, b23 = hz;
#pragma unroll
    for (int i = 0; i < 4; i++) {
        const uint4 z = Zp[i * 32 + lane];
        const unsigned e0 = __shfl_sync(0xffffffffu, ebits, i * 8 + kres);
        const unsigned e1 = __shfl_sync(0xffffffffu, ebits, i * 8 + 4 + kres);
        const __half2 h0 = *reinterpret_cast<const __half2*>(&e0);
        const __half2 h1 = *reinterpret_cast<const __half2*>(&e1);
        const __half2 zx = *reinterpret_cast<const __half2*>(&z.x);
        const __half2 zy = *reinterpret_cast<const __half2*>(&z.y);
        const __half2 zz = *reinterpret_cast<const __half2*>(&z.z);
        const __half2 zw = *reinterpret_cast<const __half2*>(&z.w);
        if (i < 2) {
            a01 = __hfma2(h0, zx, a01);
            a23 = __hfma2(h0, zy, a23);
            a01 = __hfma2(h1, zz, a01);
            a23 = __hfma2(h1, zw, a23);
        } else {
            b01 = __hfma2(h0, zx, b01);
            b23 = __hfma2(h0, zy, b23);
            b01 = __hfma2(h1, zz, b01);
            b23 = __hfma2(h1, zw, b23);
        }
    }
    const float2 fa01 = __half22float2(a01);
    const float2 fa23 = __half22float2(a23);
    const float2 fb01 = __half22float2(b01);
    const float2 fb23 = __half22float2(b23);
    float4 acc = make_float4(fa01.x + fb01.x, fa01.y + fb01.y,
                             fa23.x + fb23.x, fa23.y + fb23.y);

    acc.x += __shfl_xor_sync(0xffffffffu, acc.x, 8);
    acc.y += __shfl_xor_sync(0xffffffffu, acc.y, 8);
    acc.z += __shfl_xor_sync(0xffffffffu, acc.z, 8);
    acc.w += __shfl_xor_sync(0xffffffffu, acc.w, 8);
    acc.x += __shfl_xor_sync(0xffffffffu, acc.x, 16);
    acc.y += __shfl_xor_sync(0xffffffffu, acc.y, 16);
    acc.z += __shfl_xor_sync(0xffffffffu, acc.z, 16);
    acc.w += __shfl_xor_sync(0xffffffffu, acc.w, 16);

    if (lane < 8) {
        float* p = out + dst * 32 + lane * 4;
        asm volatile("red.global.add.v4.f32 [%0], {%1,%2,%3,%4};"
                     :: "l"(p), "f"(acc.x), "f"(acc.y), "f"(acc.z), "f"(acc.w)
                     : "memory");
    }
}

// ---------------------------------------------------------------------------
extern "C" void kernel_launch(void* const* d_in, const int* in_sizes, int n_in,
                              void* d_out, int out_size) {
    const float* x          = (const float*)d_in[0];  // [25000,32]
    const float* edge_attr  = (const float*)d_in[1];  // [400000,32]
    const float* edge_W     = (const float*)d_in[2];  // [1024,32]
    const float* node_W     = (const float*)d_in[3];  // [32,32]
    const int*   edge_index = (const int*)d_in[4];    // [2,400000]
    float* out = (float*)d_out;

    const size_t smem1 = (32 * 1024 + 32 * 72 + 32 * 33) * sizeof(float); // 144.5 KB
    cudaFuncSetAttribute(k1_build_Z, cudaFuncAttributeMaxDynamicSharedMemorySize,
                         (int)smem1);

    k1_build_Z<<<148, 256, smem1>>>(x, edge_W, node_W, out);
    k2_edges<<<EE / 8, 256>>>(edge_attr, edge_index, out);
}

// round 8
// speedup vs baseline: 1.7346x; 1.5291x over previous
#include <cuda_runtime.h>
#include <cuda_fp16.h>
#include <cstdint>

#define NN 25000
#define EE 400000
#define NTILE 12500          // EE / 32 edges per warp-tile
#define GRID 296             // 2 CTAs / SM
#define NWARPS (GRID * 8)

__device__ __forceinline__ uint32_t hmul2(uint32_t a, uint32_t b) {
    uint32_t r;
    asm("mul.rn.f16x2 %0, %1, %2;" : "=r"(r) : "r"(a), "r"(b));
    return r;
}
__device__ __forceinline__ uint32_t f2h2(float lo, float hi) {
    __half2 h = __floats2half2_rn(lo, hi);
    return *reinterpret_cast<uint32_t*>(&h);
}
__device__ __forceinline__ void mma16816(float* d,
                                         uint32_t a0, uint32_t a1,
                                         uint32_t a2, uint32_t a3,
                                         uint32_t b0, uint32_t b1) {
    asm volatile(
        "mma.sync.aligned.m16n8k16.row.col.f32.f16.f16.f32 "
        "{%0,%1,%2,%3}, {%4,%5,%6,%7}, {%8,%9}, {%0,%1,%2,%3};"
        : "+f"(d[0]), "+f"(d[1]), "+f"(d[2]), "+f"(d[3])
        : "r"(a0), "r"(a1), "r"(a2), "r"(a3), "r"(b0), "r"(b1));
}

// ---------------------------------------------------------------------------
// out = x @ node_W^T  (runs first; k_fused atomically adds messages)
// ---------------------------------------------------------------------------
__global__ void k_node(const float* __restrict__ x,
                       const float* __restrict__ node_W,
                       float* __restrict__ out) {
    __shared__ float nwT[32 * 33];
    const int t = threadIdx.x;
    for (int i = t; i < 1024; i += 256)
        nwT[(i & 31) * 33 + (i >> 5)] = node_W[i];   // nwT[d][h]
    __syncthreads();
    const int w = t >> 5, lane = t & 31;
    const int j = blockIdx.x * 8 + w;
    const float xr = x[j * 32 + lane];
    float acc = 0.f;
#pragma unroll
    for (int d = 0; d < 32; d++) {
        const float xd = __shfl_sync(0xffffffffu, xr, d);
        acc += xd * nwT[d * 33 + lane];
    }
    out[j * 32 + lane] = acc;
}

// ---------------------------------------------------------------------------
// Fused message+aggregate: per 32-edge warp-tile,
//   msgs[32,32] = P[32,1024] @ W2[1024,32]  via mma.sync m16n8k16 fp16,
//   A-frags built on the fly: splat(x_j[row,d]) * ea_frag,  B smem-resident.
// Persistent: 296 CTAs x 8 warps; B (W2) staged once per CTA, frag-ready.
// ---------------------------------------------------------------------------
__global__ void __launch_bounds__(256, 2)
k_fused(const float* __restrict__ x, const float* __restrict__ ea,
        const float* __restrict__ eW, const int* __restrict__ ei,
        float* __restrict__ out) {
    extern __shared__ uint32_t Bf[];   // 16384 u32 = 64KB, fragment-ready W2

    const int tid  = threadIdx.x;
    const int lane = tid & 31;
    const int wid  = tid >> 5;
    const int g    = lane >> 2;        // mma group row 0..7
    const int tg   = lane & 3;         // thread-in-group

    // ---- stage B fragments: Bf[((d*2+k0i)*2+np)*128 + lane*4 + r] ----
    //  r: nt = np*2 + (r>>1), rr = r&1;  n = nt*8+g;  k = k0i*16 + tg*2 + rr*8
    //  value = half2(W2[(d,k)][n], W2[(d,k+1)][n]),
    //  W2[(d,k)][h] = eW[d*1024 + h*32 + k]
    for (int i = tid; i < 16384; i += 256) {
        const int r   = i & 3;
        const int ln  = (i >> 2) & 31;
        const int np  = (i >> 7) & 1;
        const int k0i = (i >> 8) & 1;
        const int d   = i >> 9;
        const int nt  = np * 2 + (r >> 1);
        const int rr  = r & 1;
        const int n   = nt * 8 + (ln >> 2);
        const int k   = k0i * 16 + (ln & 3) * 2 + rr * 8;
        const float2 w = *reinterpret_cast<const float2*>(eW + d * 1024 + n * 32 + k);
        Bf[i] = f2h2(w.x, w.y);
    }
    __syncthreads();

    for (int tile = blockIdx.x * 8 + wid; tile < NTILE; tile += NWARPS) {
        const int e0 = tile * 32;

        // x row for this lane's edge -> 16 half2 regs
        const int src = ei[e0 + lane];
        uint32_t xh[16];
        {
            const float4* xr = reinterpret_cast<const float4*>(x + (size_t)src * 32);
#pragma unroll
            for (int q = 0; q < 8; q++) {
                const float4 v = xr[q];
                xh[q * 2]     = f2h2(v.x, v.y);
                xh[q * 2 + 1] = f2h2(v.z, v.w);
            }
        }
        // dst ids for this lane's D-frag rows
        int dsts[4];
#pragma unroll
        for (int s = 0; s < 2; s++) {
            dsts[s * 2]     = ei[EE + e0 + s * 16 + g];
            dsts[s * 2 + 1] = ei[EE + e0 + s * 16 + g + 8];
        }
        // ea fragments (register-resident): eaf[set][k0i][a0..a3]
        uint32_t eaf[2][2][4];
#pragma unroll
        for (int s = 0; s < 2; s++) {
            const float* r0 = ea + (size_t)(e0 + s * 16 + g) * 32;
            const float* r1 = r0 + 8 * 32;
#pragma unroll
            for (int k0i = 0; k0i < 2; k0i++) {
                const int c = k0i * 16 + tg * 2;
                float2 w;
                w = *reinterpret_cast<const float2*>(r0 + c);
                eaf[s][k0i][0] = f2h2(w.x, w.y);
                w = *reinterpret_cast<const float2*>(r1 + c);
                eaf[s][k0i][1] = f2h2(w.x, w.y);
                w = *reinterpret_cast<const float2*>(r0 + c + 8);
                eaf[s][k0i][2] = f2h2(w.x, w.y);
                w = *reinterpret_cast<const float2*>(r1 + c + 8);
                eaf[s][k0i][3] = f2h2(w.x, w.y);
            }
        }

        float dacc[8][4];   // [set*4 + nt][d0..d3]
#pragma unroll
        for (int q = 0; q < 8; q++)
#pragma unroll
            for (int i = 0; i < 4; i++) dacc[q][i] = 0.f;

        // -------- K loop: 32 d x 2 k-chunks --------
#pragma unroll
        for (int d = 0; d < 32; d++) {
            const uint32_t xv  = xh[d >> 1];
            const uint32_t sel = (d & 1) ? 0x3232u : 0x1010u;
            const uint32_t s0 = __byte_perm(__shfl_sync(0xffffffffu, xv, g),      0u, sel);
            const uint32_t s1 = __byte_perm(__shfl_sync(0xffffffffu, xv, g + 8),  0u, sel);
            const uint32_t s2 = __byte_perm(__shfl_sync(0xffffffffu, xv, g + 16), 0u, sel);
            const uint32_t s3 = __byte_perm(__shfl_sync(0xffffffffu, xv, g + 24), 0u, sel);
#pragma unroll
            for (int k0i = 0; k0i < 2; k0i++) {
                uint32_t A[2][4];
                A[0][0] = hmul2(s0, eaf[0][k0i][0]);
                A[0][1] = hmul2(s1, eaf[0][k0i][1]);
                A[0][2] = hmul2(s0, eaf[0][k0i][2]);
                A[0][3] = hmul2(s1, eaf[0][k0i][3]);
                A[1][0] = hmul2(s2, eaf[1][k0i][0]);
                A[1][1] = hmul2(s3, eaf[1][k0i][1]);
                A[1][2] = hmul2(s2, eaf[1][k0i][2]);
                A[1][3] = hmul2(s3, eaf[1][k0i][3]);
#pragma unroll
                for (int np = 0; np < 2; np++) {
                    const uint4 b = reinterpret_cast<const uint4*>(Bf)
                                        [((d * 2 + k0i) * 2 + np) * 32 + lane];
#pragma unroll
                    for (int s = 0; s < 2; s++) {
                        mma16816(dacc[s * 4 + np * 2 + 0],
                                 A[s][0], A[s][1], A[s][2], A[s][3], b.x, b.y);
                        mma16816(dacc[s * 4 + np * 2 + 1],
                                 A[s][0], A[s][1], A[s][2], A[s][3], b.z, b.w);
                    }
                }
            }
        }

        // -------- epilogue: scatter-add D frags --------
#pragma unroll
        for (int s = 0; s < 2; s++) {
#pragma unroll
            for (int nt = 0; nt < 4; nt++) {
                float* p0 = out + (size_t)dsts[s * 2]     * 32 + nt * 8 + tg * 2;
                float* p1 = out + (size_t)dsts[s * 2 + 1] * 32 + nt * 8 + tg * 2;
                asm volatile("red.global.add.v2.f32 [%0], {%1,%2};"
                             :: "l"(p0), "f"(dacc[s * 4 + nt][0]),
                                "f"(dacc[s * 4 + nt][1]) : "memory");
                asm volatile("red.global.add.v2.f32 [%0], {%1,%2};"
                             :: "l"(p1), "f"(dacc[s * 4 + nt][2]),
                                "f"(dacc[s * 4 + nt][3]) : "memory");
            }
        }
    }
}

// ---------------------------------------------------------------------------
extern "C" void kernel_launch(void* const* d_in, const int* in_sizes, int n_in,
                              void* d_out, int out_size) {
    const float* x          = (const float*)d_in[0];  // [25000,32]
    const float* edge_attr  = (const float*)d_in[1];  // [400000,32]
    const float* edge_W     = (const float*)d_in[2];  // [1024,32]
    const float* node_W     = (const float*)d_in[3];  // [32,32]
    const int*   edge_index = (const int*)d_in[4];    // [2,400000]
    float* out = (float*)d_out;

    cudaFuncSetAttribute(k_fused, cudaFuncAttributeMaxDynamicSharedMemorySize,
                         65536);

    k_node<<<NN / 8, 256>>>(x, node_W, out);
    k_fused<<<GRID, 256, 65536>>>(x, edge_attr, edge_W, edge_index, out);
}